// round 3
// baseline (speedup 1.0000x reference)
#include <cuda_runtime.h>
#include <cuda_bf16.h>
#include <cstdint>

// Problem constants (fixed by the reference)
#define MAXN 100000
#define MAXE 1600000
#define NPB 8          // nodes per block in the layer kernel (1 warp per node)

// ---------------- device scratch (no allocations allowed) ----------------
__device__ float g_deg[MAXN];
__device__ int   g_cnt[MAXN];
__device__ float g_dinv[MAXN];
__device__ float g_selfnorm[MAXN];
__device__ int   g_off[MAXN + 1];
__device__ int   g_cur[MAXN];
__device__ int   g_bsums[256];
__device__ int   g_csr_src[MAXE];
__device__ float g_csr_norm[MAXE];
__device__ __align__(16) float g_bufA[(size_t)MAXN * 80];
__device__ __align__(16) float g_bufB[(size_t)MAXN * 80];

// ---------------- preprocessing kernels ----------------
__global__ void k_init(int n) {
    int i = blockIdx.x * blockDim.x + threadIdx.x;
    if (i < n) { g_deg[i] = 1.0f; g_cnt[i] = 0; }
}

// NOTE: edge_index is int32 on device (JAX default x64-disabled demotes int64).
__global__ void k_edge_deg(int ecnt, const int* __restrict__ ei,
                           const float* __restrict__ ew) {
    int e = blockIdx.x * blockDim.x + threadIdx.x;
    if (e < ecnt) {
        int d = ei[ecnt + e];   // dst row
        atomicAdd(&g_deg[d], ew[e]);
        atomicAdd(&g_cnt[d], 1);
    }
}

__global__ void k_dinv(int n) {
    int i = blockIdx.x * blockDim.x + threadIdx.x;
    if (i < n) {
        float di = rsqrtf(g_deg[i]);   // deg >= 1 always (self loop fill 1.0)
        g_dinv[i] = di;
        g_selfnorm[i] = di * di;
    }
}

// Block-wise Hillis-Steele exclusive scan (1024 elems / block)
__global__ void k_scan1(int n) {
    __shared__ int sh[1024];
    int tid = threadIdx.x;
    int i = blockIdx.x * 1024 + tid;
    int v = (i < n) ? g_cnt[i] : 0;
    sh[tid] = v;
    __syncthreads();
    for (int off = 1; off < 1024; off <<= 1) {
        int t = (tid >= off) ? sh[tid - off] : 0;
        __syncthreads();
        sh[tid] += t;
        __syncthreads();
    }
    int incl = sh[tid];
    if (i < n) g_off[i] = incl - v;           // exclusive (partial)
    if (tid == 1023) g_bsums[blockIdx.x] = incl;
}

__global__ void k_scan2(int nb, int n) {
    if (threadIdx.x == 0 && blockIdx.x == 0) {
        int run = 0;
        for (int k = 0; k < nb; k++) { int t = g_bsums[k]; g_bsums[k] = run; run += t; }
        g_off[n] = run;   // = E
    }
}

__global__ void k_scan3(int n) {
    int i = blockIdx.x * blockDim.x + threadIdx.x;
    if (i < n) {
        int o = g_off[i] + g_bsums[i >> 10];
        g_off[i] = o;
        g_cur[i] = o;
    }
}

__global__ void k_scatter(int ecnt, const int* __restrict__ ei,
                          const float* __restrict__ ew) {
    int e = blockIdx.x * blockDim.x + threadIdx.x;
    if (e < ecnt) {
        int s = ei[e];
        int d = ei[ecnt + e];
        int pos = atomicAdd(&g_cur[d], 1);
        g_csr_src[pos] = s;
        g_csr_norm[pos] = g_dinv[s] * ew[e] * g_dinv[d];
    }
}

// ---------------- fused GCN layer: out = (A x) W + b  (optional relu) ----------------
// Uses A(xW) = (Ax)W: aggregate FIRST on the narrower input features, then dense matmul.
// Phase 1 (gather): one warp per node; lane l<F_IN/4 owns one float4 of the feature row.
//   Edge loop unrolled x4 -> 4 independent float4 loads in flight to hide L2 latency.
// Phase 2: block computes dense z @ W + b with W in smem.
template<int F_IN, int F_OUT, bool RELU>
__global__ void k_layer(int n, int sel_in, int sel_out,
                        const float* __restrict__ ext_in, float* ext_out,
                        const float* __restrict__ W, const float* __restrict__ b) {
    __shared__ float sW[F_IN * F_OUT];
    __shared__ float sb[F_OUT];
    __shared__ float sz[NPB][F_IN];

    const float* in = (sel_in == 0) ? g_bufA : (sel_in == 1) ? g_bufB : ext_in;
    float* out = (sel_out == 0) ? g_bufA : (sel_out == 1) ? g_bufB : ext_out;

    for (int k = threadIdx.x; k < F_IN * F_OUT; k += blockDim.x) sW[k] = W[k];
    for (int k = threadIdx.x; k < F_OUT; k += blockDim.x) sb[k] = b[k];

    int warp = threadIdx.x >> 5;
    int lane = threadIdx.x & 31;
    int node = blockIdx.x * NPB + warp;

    if (node < n) {
        int e0 = g_off[node];
        int e1 = g_off[node + 1];
        if constexpr (F_IN == 1) {
            // edge-parallel over lanes, warp reduce
            float acc = (lane == 0) ? g_selfnorm[node] * in[node] : 0.0f;
            for (int e = e0 + lane; e < e1; e += 32)
                acc += g_csr_norm[e] * __ldg(&in[g_csr_src[e]]);
            #pragma unroll
            for (int o = 16; o; o >>= 1) acc += __shfl_xor_sync(0xffffffffu, acc, o);
            if (lane == 0) sz[warp][0] = acc;
        } else {
            constexpr int F4 = F_IN / 4;          // 5,10,15,20  (all F_IN % 4 == 0)
            const float4* in4 = (const float4*)in;
            const bool act = (lane < F4);
            float4 acc = make_float4(0.f, 0.f, 0.f, 0.f);
            {
                float sn = g_selfnorm[node];
                if (act) {
                    float4 v = in4[(size_t)node * F4 + lane];
                    acc.x = sn * v.x; acc.y = sn * v.y; acc.z = sn * v.z; acc.w = sn * v.w;
                }
            }
            int e = e0;
            for (; e + 4 <= e1; e += 4) {
                int   s0 = g_csr_src[e],     s1 = g_csr_src[e + 1];
                int   s2 = g_csr_src[e + 2], s3 = g_csr_src[e + 3];
                float c0 = g_csr_norm[e],     c1 = g_csr_norm[e + 1];
                float c2 = g_csr_norm[e + 2], c3 = g_csr_norm[e + 3];
                if (act) {
                    float4 v0 = __ldg(&in4[(size_t)s0 * F4 + lane]);
                    float4 v1 = __ldg(&in4[(size_t)s1 * F4 + lane]);
                    float4 v2 = __ldg(&in4[(size_t)s2 * F4 + lane]);
                    float4 v3 = __ldg(&in4[(size_t)s3 * F4 + lane]);
                    acc.x += c0 * v0.x + c1 * v1.x + c2 * v2.x + c3 * v3.x;
                    acc.y += c0 * v0.y + c1 * v1.y + c2 * v2.y + c3 * v3.y;
                    acc.z += c0 * v0.z + c1 * v1.z + c2 * v2.z + c3 * v3.z;
                    acc.w += c0 * v0.w + c1 * v1.w + c2 * v2.w + c3 * v3.w;
                }
            }
            for (; e < e1; e++) {
                int s = g_csr_src[e];
                float c = g_csr_norm[e];
                if (act) {
                    float4 v = __ldg(&in4[(size_t)s * F4 + lane]);
                    acc.x += c * v.x; acc.y += c * v.y; acc.z += c * v.z; acc.w += c * v.w;
                }
            }
            if (act) {
                sz[warp][lane * 4 + 0] = acc.x;
                sz[warp][lane * 4 + 1] = acc.y;
                sz[warp][lane * 4 + 2] = acc.z;
                sz[warp][lane * 4 + 3] = acc.w;
            }
        }
    }
    __syncthreads();

    // Phase 2: NPB*F_OUT outputs per block
    for (int idx = threadIdx.x; idx < NPB * F_OUT; idx += blockDim.x) {
        int wnode = idx / F_OUT;
        int j = idx - wnode * F_OUT;
        int nd = blockIdx.x * NPB + wnode;
        if (nd < n) {
            float a = sb[j];
            #pragma unroll 4
            for (int f = 0; f < F_IN; f++) a += sz[wnode][f] * sW[f * F_OUT + j];
            if (RELU) a = fmaxf(a, 0.0f);
            out[(size_t)nd * F_OUT + j] = a;
        }
    }
}

// ---------------- launch ----------------
extern "C" void kernel_launch(void* const* d_in, const int* in_sizes, int n_in,
                              void* d_out, int out_size) {
    const float* x  = (const float*)d_in[0];
    const int*   ei = (const int*)d_in[1];     // int32! (JAX demotes int64)
    const float* ew = (const float*)d_in[2];
    const float* W1 = (const float*)d_in[3];  const float* b1 = (const float*)d_in[4];
    const float* W2 = (const float*)d_in[5];  const float* b2 = (const float*)d_in[6];
    const float* W3 = (const float*)d_in[7];  const float* b3 = (const float*)d_in[8];
    const float* W4 = (const float*)d_in[9];  const float* b4 = (const float*)d_in[10];
    const float* W5 = (const float*)d_in[11]; const float* b5 = (const float*)d_in[12];
    float* out = (float*)d_out;

    int n = in_sizes[0];       // x is [N,1]
    int e = in_sizes[2];       // edge_weights is [E]

    int tb = 256;
    int gbN = (n + tb - 1) / tb;
    int gbE = (e + tb - 1) / tb;
    int nb  = (n + 1023) / 1024;

    // degree + count
    k_init<<<gbN, tb>>>(n);
    k_edge_deg<<<gbE, tb>>>(e, ei, ew);
    k_dinv<<<gbN, tb>>>(n);

    // CSR build (counting sort by dst)
    k_scan1<<<nb, 1024>>>(n);
    k_scan2<<<1, 32>>>(nb, n);
    k_scan3<<<gbN, tb>>>(n);
    k_scatter<<<gbE, tb>>>(e, ei, ew);

    // 5 fused layers: ping-pong bufA/bufB; last writes relu to d_out
    int gbL = (n + NPB - 1) / NPB;
    k_layer<1,  20,  false><<<gbL, 256>>>(n, 2, 0, x,       nullptr, W1, b1);
    k_layer<20, 40,  false><<<gbL, 256>>>(n, 0, 1, nullptr, nullptr, W2, b2);
    k_layer<40, 60,  false><<<gbL, 256>>>(n, 1, 0, nullptr, nullptr, W3, b3);
    k_layer<60, 80,  false><<<gbL, 256>>>(n, 0, 1, nullptr, nullptr, W4, b4);
    k_layer<80, 100, true ><<<gbL, 256>>>(n, 1, 2, nullptr, out,     W5, b5);
    (void)n_in; (void)out_size;
}

// round 4
// speedup vs baseline: 4.0642x; 4.0642x over previous
#include <cuda_runtime.h>
#include <cuda_bf16.h>
#include <cstdint>

#define MAXN 100000
#define MAXE 1600000

// ---------------- device scratch (no allocations allowed) ----------------
__device__ float g_deg[MAXN];
__device__ int   g_cnt[MAXN];
__device__ float g_dinv[MAXN];
__device__ float g_selfnorm[MAXN];
__device__ int   g_off[MAXN + 1];
__device__ int   g_cur[MAXN];
__device__ int   g_bsums[256];
__device__ int   g_csr_src[MAXE];
__device__ float g_csr_norm[MAXE];
__device__ float2 g_p[6][MAXN];     // pass states: p[k] = (A^k x, A^k 1)
__device__ float  g_c[6 * 128];     // coef rows: c5, d4, d3, d2, d1, b5 (each <=100)

// ---------------- preprocessing ----------------
__global__ void k_init(int n) {
    int i = blockIdx.x * blockDim.x + threadIdx.x;
    if (i < n) { g_deg[i] = 1.0f; g_cnt[i] = 0; }
}

// edge_index is int32 on device (JAX x64-disabled demotes int64).
__global__ void k_edge_deg(int ecnt, const int* __restrict__ ei,
                           const float* __restrict__ ew) {
    int e = blockIdx.x * blockDim.x + threadIdx.x;
    if (e < ecnt) {
        int d = ei[ecnt + e];
        atomicAdd(&g_deg[d], ew[e]);
        atomicAdd(&g_cnt[d], 1);
    }
}

// dinv/selfnorm + initial state p0 = (x, 1)
__global__ void k_dinv(int n, const float* __restrict__ x) {
    int i = blockIdx.x * blockDim.x + threadIdx.x;
    if (i < n) {
        float di = rsqrtf(g_deg[i]);      // deg >= 1 (self loop fill 1.0)
        g_dinv[i] = di;
        g_selfnorm[i] = di * di;
        g_p[0][i] = make_float2(x[i], 1.0f);
    }
}

__global__ void k_scan1(int n) {
    __shared__ int sh[1024];
    int tid = threadIdx.x;
    int i = blockIdx.x * 1024 + tid;
    int v = (i < n) ? g_cnt[i] : 0;
    sh[tid] = v;
    __syncthreads();
    for (int off = 1; off < 1024; off <<= 1) {
        int t = (tid >= off) ? sh[tid - off] : 0;
        __syncthreads();
        sh[tid] += t;
        __syncthreads();
    }
    int incl = sh[tid];
    if (i < n) g_off[i] = incl - v;
    if (tid == 1023) g_bsums[blockIdx.x] = incl;
}

__global__ void k_scan2(int nb, int n) {
    if (threadIdx.x == 0 && blockIdx.x == 0) {
        int run = 0;
        for (int k = 0; k < nb; k++) { int t = g_bsums[k]; g_bsums[k] = run; run += t; }
        g_off[n] = run;
    }
}

__global__ void k_scan3(int n) {
    int i = blockIdx.x * blockDim.x + threadIdx.x;
    if (i < n) {
        int o = g_off[i] + g_bsums[i >> 10];
        g_off[i] = o;
        g_cur[i] = o;
    }
}

__global__ void k_scatter(int ecnt, const int* __restrict__ ei,
                          const float* __restrict__ ew) {
    int e = blockIdx.x * blockDim.x + threadIdx.x;
    if (e < ecnt) {
        int s = ei[e];
        int d = ei[ecnt + e];
        int pos = atomicAdd(&g_cur[d], 1);
        g_csr_src[pos] = s;
        g_csr_norm[pos] = g_dinv[s] * ew[e] * g_dinv[d];
    }
}

// ---------------- coefficient rows (single block, 128 threads) ----------------
// c5 = W1W2W3W4W5 ; d4 = b1W2W3W4W5 ; d3 = b2W3W4W5 ; d2 = b3W4W5 ; d1 = b4W5 ; row5 = b5
__device__ __forceinline__ void mv_row(const float* in, const float* W,
                                       int IN, int OUT, float* out, int j) {
    if (j < OUT) {
        float s = 0.0f;
        for (int k = 0; k < IN; k++) s += in[k] * W[k * OUT + j];
        out[j] = s;
    }
}

__global__ void k_weights(const float* __restrict__ W1, const float* __restrict__ b1,
                          const float* __restrict__ W2, const float* __restrict__ b2,
                          const float* __restrict__ W3, const float* __restrict__ b3,
                          const float* __restrict__ W4, const float* __restrict__ b4,
                          const float* __restrict__ W5, const float* __restrict__ b5) {
    __shared__ float a[128], t[128];
    int j = threadIdx.x;

    // c5: W1 (1x20) -> W2 -> W3 -> W4 -> W5
    if (j < 20) a[j] = W1[j];
    __syncthreads();
    mv_row(a, W2, 20, 40, t, j);  __syncthreads();
    mv_row(t, W3, 40, 60, a, j);  __syncthreads();
    mv_row(a, W4, 60, 80, t, j);  __syncthreads();
    mv_row(t, W5, 80, 100, &g_c[0 * 128], j); __syncthreads();

    // d4: b1 -> W2..W5
    if (j < 20) a[j] = b1[j];
    __syncthreads();
    mv_row(a, W2, 20, 40, t, j);  __syncthreads();
    mv_row(t, W3, 40, 60, a, j);  __syncthreads();
    mv_row(a, W4, 60, 80, t, j);  __syncthreads();
    mv_row(t, W5, 80, 100, &g_c[1 * 128], j); __syncthreads();

    // d3: b2 -> W3..W5
    if (j < 40) a[j] = b2[j];
    __syncthreads();
    mv_row(a, W3, 40, 60, t, j);  __syncthreads();
    mv_row(t, W4, 60, 80, a, j);  __syncthreads();
    mv_row(a, W5, 80, 100, &g_c[2 * 128], j); __syncthreads();

    // d2: b3 -> W4, W5
    if (j < 60) a[j] = b3[j];
    __syncthreads();
    mv_row(a, W4, 60, 80, t, j);  __syncthreads();
    mv_row(t, W5, 80, 100, &g_c[3 * 128], j); __syncthreads();

    // d1: b4 -> W5
    if (j < 80) a[j] = b4[j];
    __syncthreads();
    mv_row(a, W5, 80, 100, &g_c[4 * 128], j); __syncthreads();

    if (j < 100) g_c[5 * 128 + j] = b5[j];
}

// ---------------- scalar float2 SpMV: p_out = A p_in ----------------
__global__ void k_spmv(int n, int kin, int kout) {
    int i = blockIdx.x * blockDim.x + threadIdx.x;
    if (i >= n) return;
    const float2* __restrict__ vin = g_p[kin];
    int e0 = g_off[i];
    int e1 = g_off[i + 1];
    float sn = g_selfnorm[i];
    float2 v = vin[i];
    float ax = sn * v.x, ay = sn * v.y;
    int e = e0;
    for (; e + 4 <= e1; e += 4) {
        int   s0 = g_csr_src[e],     s1 = g_csr_src[e + 1];
        int   s2 = g_csr_src[e + 2], s3 = g_csr_src[e + 3];
        float c0 = g_csr_norm[e],     c1 = g_csr_norm[e + 1];
        float c2 = g_csr_norm[e + 2], c3 = g_csr_norm[e + 3];
        float2 w0 = __ldg(&vin[s0]);
        float2 w1 = __ldg(&vin[s1]);
        float2 w2 = __ldg(&vin[s2]);
        float2 w3 = __ldg(&vin[s3]);
        ax += c0 * w0.x + c1 * w1.x + c2 * w2.x + c3 * w3.x;
        ay += c0 * w0.y + c1 * w1.y + c2 * w2.y + c3 * w3.y;
    }
    for (; e < e1; e++) {
        int s = g_csr_src[e];
        float c = g_csr_norm[e];
        float2 w = __ldg(&vin[s]);
        ax += c * w.x;
        ay += c * w.y;
    }
    g_p[kout][i] = make_float2(ax, ay);
}

// ---------------- final dense write-out: out[n][j] = relu(sum_k state*coef) ----------------
__global__ void k_final(int n, float* __restrict__ out) {
    __shared__ float sc[6][100];
    for (int t = threadIdx.x; t < 600; t += blockDim.x)
        sc[t / 100][t % 100] = g_c[(t / 100) * 128 + (t % 100)];
    __syncthreads();

    int idx = blockIdx.x * blockDim.x + threadIdx.x;   // node*25 + chunk
    int node = idx / 25;
    int ch = idx - node * 25;
    if (node >= n) return;

    float v5 = g_p[5][node].x;
    float a4 = g_p[4][node].y;
    float a3 = g_p[3][node].y;
    float a2 = g_p[2][node].y;
    float a1 = g_p[1][node].y;

    int j0 = ch * 4;
    float4 r;
    r.x = fmaxf(v5 * sc[0][j0+0] + a4 * sc[1][j0+0] + a3 * sc[2][j0+0] + a2 * sc[3][j0+0] + a1 * sc[4][j0+0] + sc[5][j0+0], 0.0f);
    r.y = fmaxf(v5 * sc[0][j0+1] + a4 * sc[1][j0+1] + a3 * sc[2][j0+1] + a2 * sc[3][j0+1] + a1 * sc[4][j0+1] + sc[5][j0+1], 0.0f);
    r.z = fmaxf(v5 * sc[0][j0+2] + a4 * sc[1][j0+2] + a3 * sc[2][j0+2] + a2 * sc[3][j0+2] + a1 * sc[4][j0+2] + sc[5][j0+2], 0.0f);
    r.w = fmaxf(v5 * sc[0][j0+3] + a4 * sc[1][j0+3] + a3 * sc[2][j0+3] + a2 * sc[3][j0+3] + a1 * sc[4][j0+3] + sc[5][j0+3], 0.0f);
    // row stride 100 floats = 400B (16B-multiple), chunk offset 16B -> aligned float4 store
    ((float4*)(out + (size_t)node * 100))[ch] = r;
}

// ---------------- launch ----------------
extern "C" void kernel_launch(void* const* d_in, const int* in_sizes, int n_in,
                              void* d_out, int out_size) {
    const float* x  = (const float*)d_in[0];
    const int*   ei = (const int*)d_in[1];     // int32!
    const float* ew = (const float*)d_in[2];
    const float* W1 = (const float*)d_in[3];  const float* b1 = (const float*)d_in[4];
    const float* W2 = (const float*)d_in[5];  const float* b2 = (const float*)d_in[6];
    const float* W3 = (const float*)d_in[7];  const float* b3 = (const float*)d_in[8];
    const float* W4 = (const float*)d_in[9];  const float* b4 = (const float*)d_in[10];
    const float* W5 = (const float*)d_in[11]; const float* b5 = (const float*)d_in[12];
    float* out = (float*)d_out;

    int n = in_sizes[0];
    int e = in_sizes[2];

    int tb = 256;
    int gbN = (n + tb - 1) / tb;
    int gbE = (e + tb - 1) / tb;
    int nb  = (n + 1023) / 1024;

    k_init<<<gbN, tb>>>(n);
    k_edge_deg<<<gbE, tb>>>(e, ei, ew);
    k_dinv<<<gbN, tb>>>(n, x);

    k_scan1<<<nb, 1024>>>(n);
    k_scan2<<<1, 32>>>(nb, n);
    k_scan3<<<gbN, tb>>>(n);
    k_scatter<<<gbE, tb>>>(e, ei, ew);

    k_weights<<<1, 128>>>(W1, b1, W2, b2, W3, b3, W4, b4, W5, b5);

    // 5 scalar float2 SpMV passes: p[k] = A p[k-1]
    k_spmv<<<gbN, tb>>>(n, 0, 1);
    k_spmv<<<gbN, tb>>>(n, 1, 2);
    k_spmv<<<gbN, tb>>>(n, 2, 3);
    k_spmv<<<gbN, tb>>>(n, 3, 4);
    k_spmv<<<gbN, tb>>>(n, 4, 5);

    int tot = n * 25;
    k_final<<<(tot + tb - 1) / tb, tb>>>(n, out);

    (void)n_in; (void)out_size;
}

// round 5
// speedup vs baseline: 4.6150x; 1.1355x over previous
#include <cuda_runtime.h>
#include <cuda_bf16.h>
#include <cstdint>

#define MAXN 100000
#define MAXE 1600000

// ---------------- device scratch (no allocations allowed) ----------------
__device__ float g_deg[MAXN];
__device__ int   g_cnt[MAXN];
__device__ float g_dinv[MAXN];
__device__ float g_selfnorm[MAXN];
__device__ int   g_off[MAXN + 1];
__device__ int   g_cur[MAXN];
__device__ int   g_bsums[128];
__device__ int2  g_csr[MAXE];        // packed {src, __float_as_int(norm)}
__device__ float2 g_p[5][MAXN];      // states: indices 1..4 used: p[k] = (A^k x, A^k 1)
__device__ float  g_c[6 * 128];      // coef rows: c5, d4, d3, d2, d1, b5

// ---------------- preprocessing ----------------
__global__ void k_init(int n) {
    int i = blockIdx.x * blockDim.x + threadIdx.x;
    if (i < n) { g_deg[i] = 1.0f; g_cnt[i] = 0; }
}

// edge_index is int32 on device (JAX x64-disabled demotes int64).
__global__ void k_edge_deg(int ecnt, const int* __restrict__ ei,
                           const float* __restrict__ ew) {
    int e = blockIdx.x * blockDim.x + threadIdx.x;
    if (e < ecnt) {
        int d = ei[ecnt + e];
        atomicAdd(&g_deg[d], ew[e]);
        atomicAdd(&g_cnt[d], 1);
    }
}

// Block scan over 1024 counts (partial exclusive + per-block sums)
__global__ void k_scan1(int n) {
    __shared__ int sh[1024];
    int tid = threadIdx.x;
    int i = blockIdx.x * 1024 + tid;
    int v = (i < n) ? g_cnt[i] : 0;
    sh[tid] = v;
    __syncthreads();
    for (int off = 1; off < 1024; off <<= 1) {
        int t = (tid >= off) ? sh[tid - off] : 0;
        __syncthreads();
        sh[tid] += t;
        __syncthreads();
    }
    int incl = sh[tid];
    if (i < n) g_off[i] = incl - v;
    if (tid == 1023) g_bsums[blockIdx.x] = incl;
}

// Fused: bsums scan (nb<=128) + final offsets + dinv/selfnorm (p0 not materialized)
__global__ void k_scan3f(int n, int nb) {
    __shared__ int sb[128];
    int tid = threadIdx.x;
    if (tid < 128) sb[tid] = (tid < nb) ? g_bsums[tid] : 0;
    __syncthreads();
    for (int off = 1; off < 128; off <<= 1) {
        int t = (tid >= off && tid < 128) ? sb[tid - off] : 0;
        __syncthreads();
        if (tid < 128) sb[tid] += t;
        __syncthreads();
    }
    if (blockIdx.x == 0 && tid == 0) g_off[n] = sb[nb - 1];
    int i = blockIdx.x * blockDim.x + tid;
    if (i < n) {
        int blk = i >> 10;
        int o = g_off[i] + (blk ? sb[blk - 1] : 0);
        g_off[i] = o;
        g_cur[i] = o;
        float di = rsqrtf(g_deg[i]);      // deg >= 1 (self loop fill 1.0)
        g_dinv[i] = di;
        g_selfnorm[i] = di * di;
    }
}

__global__ void k_scatter(int ecnt, const int* __restrict__ ei,
                          const float* __restrict__ ew) {
    int e = blockIdx.x * blockDim.x + threadIdx.x;
    if (e < ecnt) {
        int s = ei[e];
        int d = ei[ecnt + e];
        int pos = atomicAdd(&g_cur[d], 1);
        float norm = g_dinv[s] * ew[e] * g_dinv[d];
        g_csr[pos] = make_int2(s, __float_as_int(norm));  // single 8B store
    }
}

// ---------------- coefficient chain (device fn, run by block 0 of pass 1) ----------------
// c5 = W1W2W3W4W5 ; d4 = b1W2W3W4W5 ; d3 = b2W3W4W5 ; d2 = b3W4W5 ; d1 = b4W5 ; row5 = b5
__device__ __forceinline__ void mv_row(const float* in, const float* W,
                                       int IN, int OUT, float* out, int j) {
    if (j < OUT) {
        float s = 0.0f;
        for (int k = 0; k < IN; k++) s += in[k] * W[k * OUT + j];
        out[j] = s;
    }
}

__device__ void weights_chain(const float* W1, const float* b1, const float* W2, const float* b2,
                              const float* W3, const float* b3, const float* W4, const float* b4,
                              const float* W5, const float* b5) {
    __shared__ float a[128], t[128];
    int j = threadIdx.x;   // blockDim may exceed 128; guards handle it

    if (j < 20) a[j] = W1[j];
    __syncthreads();
    mv_row(a, W2, 20, 40, t, j);  __syncthreads();
    mv_row(t, W3, 40, 60, a, j);  __syncthreads();
    mv_row(a, W4, 60, 80, t, j);  __syncthreads();
    mv_row(t, W5, 80, 100, &g_c[0 * 128], j); __syncthreads();

    if (j < 20) a[j] = b1[j];
    __syncthreads();
    mv_row(a, W2, 20, 40, t, j);  __syncthreads();
    mv_row(t, W3, 40, 60, a, j);  __syncthreads();
    mv_row(a, W4, 60, 80, t, j);  __syncthreads();
    mv_row(t, W5, 80, 100, &g_c[1 * 128], j); __syncthreads();

    if (j < 40) a[j] = b2[j];
    __syncthreads();
    mv_row(a, W3, 40, 60, t, j);  __syncthreads();
    mv_row(t, W4, 60, 80, a, j);  __syncthreads();
    mv_row(a, W5, 80, 100, &g_c[2 * 128], j); __syncthreads();

    if (j < 60) a[j] = b3[j];
    __syncthreads();
    mv_row(a, W4, 60, 80, t, j);  __syncthreads();
    mv_row(t, W5, 80, 100, &g_c[3 * 128], j); __syncthreads();

    if (j < 80) a[j] = b4[j];
    __syncthreads();
    mv_row(a, W5, 80, 100, &g_c[4 * 128], j); __syncthreads();

    if (j < 100) g_c[5 * 128 + j] = b5[j];
}

// ---------------- pass 1: p1 = A (x, 1). y needs NO gather; x gathers are scalar. ----------------
__global__ void k_spmv1(int n, const float* __restrict__ x,
                        const float* __restrict__ W1, const float* __restrict__ b1,
                        const float* __restrict__ W2, const float* __restrict__ b2,
                        const float* __restrict__ W3, const float* __restrict__ b3,
                        const float* __restrict__ W4, const float* __restrict__ b4,
                        const float* __restrict__ W5, const float* __restrict__ b5) {
    if (blockIdx.x == 0)
        weights_chain(W1, b1, W2, b2, W3, b3, W4, b4, W5, b5);

    int i = blockIdx.x * blockDim.x + threadIdx.x;
    if (i >= n) return;
    int e0 = g_off[i], e1 = g_off[i + 1];
    float sn = g_selfnorm[i];
    float ax = sn * __ldg(&x[i]);
    float ay = sn;
    int e = e0;
    for (; e + 4 <= e1; e += 4) {
        int2 p0 = __ldg(&g_csr[e]);
        int2 p1 = __ldg(&g_csr[e + 1]);
        int2 p2 = __ldg(&g_csr[e + 2]);
        int2 p3 = __ldg(&g_csr[e + 3]);
        float c0 = __int_as_float(p0.y), c1 = __int_as_float(p1.y);
        float c2 = __int_as_float(p2.y), c3 = __int_as_float(p3.y);
        float v0 = __ldg(&x[p0.x]);
        float v1 = __ldg(&x[p1.x]);
        float v2 = __ldg(&x[p2.x]);
        float v3 = __ldg(&x[p3.x]);
        ax += c0 * v0 + c1 * v1 + c2 * v2 + c3 * v3;
        ay += c0 + c1 + c2 + c3;
    }
    for (; e < e1; e++) {
        int2 p = __ldg(&g_csr[e]);
        float c = __int_as_float(p.y);
        ax += c * __ldg(&x[p.x]);
        ay += c;
    }
    g_p[1][i] = make_float2(ax, ay);
}

// ---------------- generic float2 pass: p[kout] = A p[kin] ----------------
__global__ void k_spmv(int n, int kin, int kout) {
    int i = blockIdx.x * blockDim.x + threadIdx.x;
    if (i >= n) return;
    const float2* __restrict__ vin = g_p[kin];
    int e0 = g_off[i], e1 = g_off[i + 1];
    float sn = g_selfnorm[i];
    float2 v = vin[i];
    float ax = sn * v.x, ay = sn * v.y;
    int e = e0;
    for (; e + 4 <= e1; e += 4) {
        int2 p0 = __ldg(&g_csr[e]);
        int2 p1 = __ldg(&g_csr[e + 1]);
        int2 p2 = __ldg(&g_csr[e + 2]);
        int2 p3 = __ldg(&g_csr[e + 3]);
        float c0 = __int_as_float(p0.y), c1 = __int_as_float(p1.y);
        float c2 = __int_as_float(p2.y), c3 = __int_as_float(p3.y);
        float2 w0 = __ldg(&vin[p0.x]);
        float2 w1 = __ldg(&vin[p1.x]);
        float2 w2 = __ldg(&vin[p2.x]);
        float2 w3 = __ldg(&vin[p3.x]);
        ax += c0 * w0.x + c1 * w1.x + c2 * w2.x + c3 * w3.x;
        ay += c0 * w0.y + c1 * w1.y + c2 * w2.y + c3 * w3.y;
    }
    for (; e < e1; e++) {
        int2 p = __ldg(&g_csr[e]);
        float c = __int_as_float(p.y);
        float2 w = __ldg(&vin[p.x]);
        ax += c * w.x;
        ay += c * w.y;
    }
    g_p[kout][i] = make_float2(ax, ay);
}

// ---------------- pass 5 (x-only) fused with final dense write-out ----------------
__global__ void k_spmv5_final(int n, float* __restrict__ out) {
    __shared__ float sc[6][100];
    __shared__ float sv5[256], sa1[256], sa2[256], sa3[256], sa4[256];
    for (int t = threadIdx.x; t < 600; t += blockDim.x)
        sc[t / 100][t % 100] = g_c[(t / 100) * 128 + (t % 100)];

    int base = blockIdx.x * 256;
    int i = base + threadIdx.x;

    // Phase A: scalar SpMV for v5 = (A p4).x ; stash a1..a4
    if (i < n) {
        const float2* __restrict__ vin = g_p[4];
        int e0 = g_off[i], e1 = g_off[i + 1];
        float ax = g_selfnorm[i] * vin[i].x;
        int e = e0;
        for (; e + 4 <= e1; e += 4) {
            int2 p0 = __ldg(&g_csr[e]);
            int2 p1 = __ldg(&g_csr[e + 1]);
            int2 p2 = __ldg(&g_csr[e + 2]);
            int2 p3 = __ldg(&g_csr[e + 3]);
            float v0 = __ldg(&vin[p0.x].x);
            float v1 = __ldg(&vin[p1.x].x);
            float v2 = __ldg(&vin[p2.x].x);
            float v3 = __ldg(&vin[p3.x].x);
            ax += __int_as_float(p0.y) * v0 + __int_as_float(p1.y) * v1
                + __int_as_float(p2.y) * v2 + __int_as_float(p3.y) * v3;
        }
        for (; e < e1; e++) {
            int2 p = __ldg(&g_csr[e]);
            ax += __int_as_float(p.y) * __ldg(&vin[p.x].x);
        }
        sv5[threadIdx.x] = ax;
        sa1[threadIdx.x] = g_p[1][i].y;
        sa2[threadIdx.x] = g_p[2][i].y;
        sa3[threadIdx.x] = g_p[3][i].y;
        sa4[threadIdx.x] = g_p[4][i].y;
    }
    __syncthreads();

    // Phase B: 256 nodes x 25 float4 chunks, coalesced stores
    for (int t = threadIdx.x; t < 256 * 25; t += blockDim.x) {
        int wnode = t / 25;
        int ch = t - wnode * 25;
        int node = base + wnode;
        if (node >= n) break;
        float v5 = sv5[wnode];
        float a1 = sa1[wnode], a2 = sa2[wnode], a3 = sa3[wnode], a4 = sa4[wnode];
        int j0 = ch * 4;
        float4 r;
        float* rr = &r.x;
        #pragma unroll
        for (int q = 0; q < 4; q++) {
            int j = j0 + q;
            rr[q] = fmaxf(v5 * sc[0][j] + a4 * sc[1][j] + a3 * sc[2][j]
                        + a2 * sc[3][j] + a1 * sc[4][j] + sc[5][j], 0.0f);
        }
        ((float4*)(out + (size_t)node * 100))[ch] = r;
    }
}

// ---------------- launch ----------------
extern "C" void kernel_launch(void* const* d_in, const int* in_sizes, int n_in,
                              void* d_out, int out_size) {
    const float* x  = (const float*)d_in[0];
    const int*   ei = (const int*)d_in[1];     // int32!
    const float* ew = (const float*)d_in[2];
    const float* W1 = (const float*)d_in[3];  const float* b1 = (const float*)d_in[4];
    const float* W2 = (const float*)d_in[5];  const float* b2 = (const float*)d_in[6];
    const float* W3 = (const float*)d_in[7];  const float* b3 = (const float*)d_in[8];
    const float* W4 = (const float*)d_in[9];  const float* b4 = (const float*)d_in[10];
    const float* W5 = (const float*)d_in[11]; const float* b5 = (const float*)d_in[12];
    float* out = (float*)d_out;

    int n = in_sizes[0];
    int e = in_sizes[2];

    int tb = 256;
    int gbN = (n + tb - 1) / tb;
    int gbE = (e + tb - 1) / tb;
    int nb  = (n + 1023) / 1024;

    k_init<<<gbN, tb>>>(n);
    k_edge_deg<<<gbE, tb>>>(e, ei, ew);
    k_scan1<<<nb, 1024>>>(n);
    k_scan3f<<<gbN, tb>>>(n, nb);
    k_scatter<<<gbE, tb>>>(e, ei, ew);

    k_spmv1<<<gbN, tb>>>(n, x, W1, b1, W2, b2, W3, b3, W4, b4, W5, b5);
    k_spmv<<<gbN, tb>>>(n, 1, 2);
    k_spmv<<<gbN, tb>>>(n, 2, 3);
    k_spmv<<<gbN, tb>>>(n, 3, 4);
    k_spmv5_final<<<gbN, tb>>>(n, out);

    (void)n_in; (void)out_size;
}

// round 6
// speedup vs baseline: 4.7618x; 1.0318x over previous
#include <cuda_runtime.h>
#include <cuda_bf16.h>
#include <cstdint>

#define MAXN 100000
#define MAXE 1600000
#define E2CAP (MAXE + MAXN + 8)
#define FPS 67108864.0f            // 2^26 fixed-point scale for weighted degree

// ---------------- device scratch (no allocations allowed) ----------------
__device__ unsigned long long g_pk[MAXN];   // packed: cnt<<46 | fixedpoint(weighted deg-1)
__device__ float g_dinv[MAXN];
__device__ int   g_off[MAXN + 1];
__device__ int   g_cur[MAXN];
__device__ int   g_bsums[128];
__device__ __align__(16) int2 g_csr[E2CAP];   // {src, __float_as_int(norm)}; row head = self edge
__device__ __align__(16) int  g_dsta[E2CAP];  // dst per edge (sorted ascending)
__device__ float2 g_p[5][MAXN];     // states 1..4: p[k] = (A^k x, A^k 1)
__device__ float  g_c[6 * 128];     // coef rows: c5, d4, d3, d2, d1, b5

// ---------------- preprocessing ----------------
__global__ void k_init(int n) {
    int i = blockIdx.x * blockDim.x + threadIdx.x;
    if (i < n) {
        g_pk[i] = 0ULL;
        float2 z = make_float2(0.f, 0.f);
        g_p[1][i] = z; g_p[2][i] = z; g_p[3][i] = z; g_p[4][i] = z;
    }
}

// edge_index is int32 on device (JAX x64-disabled demotes int64).
// Single packed 64-bit atomic: count in bits 46+, weighted degree (2^26 fixed) below.
__global__ void k_edge_deg(int ecnt, const int* __restrict__ ei,
                           const float* __restrict__ ew) {
    int e = blockIdx.x * blockDim.x + threadIdx.x;
    if (e < ecnt) {
        int d = ei[ecnt + e];
        unsigned long long v = (unsigned long long)(ew[e] * FPS + 0.5f) | (1ULL << 46);
        atomicAdd(&g_pk[d], v);
    }
}

// Block scan over 1024 counts (partial exclusive + per-block sums)
__global__ void k_scan1(int n) {
    __shared__ int sh[1024];
    int tid = threadIdx.x;
    int i = blockIdx.x * 1024 + tid;
    int v = (i < n) ? (int)(g_pk[i] >> 46) : 0;
    sh[tid] = v;
    __syncthreads();
    for (int off = 1; off < 1024; off <<= 1) {
        int t = (tid >= off) ? sh[tid - off] : 0;
        __syncthreads();
        sh[tid] += t;
        __syncthreads();
    }
    int incl = sh[tid];
    if (i < n) g_off[i] = incl - v;
    if (tid == 1023) g_bsums[blockIdx.x] = incl;
}

// Fused: bsums scan + final offsets (+i self slots) + dinv + self-edge emit + pads
__global__ void k_scan3f(int n, int nb, int e2) {
    __shared__ int sb[128];
    int tid = threadIdx.x;
    if (tid < 128) sb[tid] = (tid < nb) ? g_bsums[tid] : 0;
    __syncthreads();
    for (int off = 1; off < 128; off <<= 1) {
        int t = (tid >= off && tid < 128) ? sb[tid - off] : 0;
        __syncthreads();
        if (tid < 128) sb[tid] += t;
        __syncthreads();
    }
    if (blockIdx.x == 0) {
        if (tid == 0) g_off[n] = sb[nb - 1] + n;
        if (tid < 8) {                       // pad so edge kernels need no tail guard
            g_csr[e2 + tid] = make_int2(0, 0);   // norm = 0 -> contributes nothing
            g_dsta[e2 + tid] = n - 1;
        }
    }
    int i = blockIdx.x * blockDim.x + tid;
    if (i < n) {
        int blk = i >> 10;
        int o = g_off[i] + (blk ? sb[blk - 1] : 0) + i;   // +i: one self slot per prior node
        unsigned long long pk = g_pk[i];
        float deg = 1.0f + (float)(pk & ((1ULL << 46) - 1ULL)) * (1.0f / FPS);
        float di = rsqrtf(deg);
        g_dinv[i] = di;
        g_off[i] = o;
        g_cur[i] = o + 1;                                  // real edges start after self edge
        g_csr[o] = make_int2(i, __float_as_int(di * di));  // self edge, norm = dinv^2
        g_dsta[o] = i;
    }
}

__global__ void k_scatter(int ecnt, const int* __restrict__ ei,
                          const float* __restrict__ ew) {
    int e = blockIdx.x * blockDim.x + threadIdx.x;
    if (e < ecnt) {
        int s = ei[e];
        int d = ei[ecnt + e];
        int pos = atomicAdd(&g_cur[d], 1);
        float norm = g_dinv[s] * ew[e] * g_dinv[d];
        g_csr[pos] = make_int2(s, __float_as_int(norm));
        g_dsta[pos] = d;
    }
}

// ---------------- coefficient chain (device fn, run by block 0 of pass 1) ----------------
__device__ __forceinline__ void mv_row(const float* in, const float* W,
                                       int IN, int OUT, float* out, int j) {
    if (j < OUT) {
        float s = 0.0f;
        for (int k = 0; k < IN; k++) s += in[k] * W[k * OUT + j];
        out[j] = s;
    }
}

__device__ void weights_chain(const float* W1, const float* b1, const float* W2, const float* b2,
                              const float* W3, const float* b3, const float* W4, const float* b4,
                              const float* W5, const float* b5) {
    __shared__ float a[128], t[128];
    int j = threadIdx.x;

    if (j < 20) a[j] = W1[j];
    __syncthreads();
    mv_row(a, W2, 20, 40, t, j);  __syncthreads();
    mv_row(t, W3, 40, 60, a, j);  __syncthreads();
    mv_row(a, W4, 60, 80, t, j);  __syncthreads();
    mv_row(t, W5, 80, 100, &g_c[0 * 128], j); __syncthreads();

    if (j < 20) a[j] = b1[j];
    __syncthreads();
    mv_row(a, W2, 20, 40, t, j);  __syncthreads();
    mv_row(t, W3, 40, 60, a, j);  __syncthreads();
    mv_row(a, W4, 60, 80, t, j);  __syncthreads();
    mv_row(t, W5, 80, 100, &g_c[1 * 128], j); __syncthreads();

    if (j < 40) a[j] = b2[j];
    __syncthreads();
    mv_row(a, W3, 40, 60, t, j);  __syncthreads();
    mv_row(t, W4, 60, 80, a, j);  __syncthreads();
    mv_row(a, W5, 80, 100, &g_c[2 * 128], j); __syncthreads();

    if (j < 60) a[j] = b3[j];
    __syncthreads();
    mv_row(a, W4, 60, 80, t, j);  __syncthreads();
    mv_row(t, W5, 80, 100, &g_c[3 * 128], j); __syncthreads();

    if (j < 80) a[j] = b4[j];
    __syncthreads();
    mv_row(a, W5, 80, 100, &g_c[4 * 128], j); __syncthreads();

    if (j < 100) g_c[5 * 128 + j] = b5[j];
}

// ---------------- edge-parallel pass 1: p1 += per-edge {c*x[src], c} ----------------
__global__ void k_epass1(int e2, const float* __restrict__ x,
                         const float* __restrict__ W1, const float* __restrict__ b1,
                         const float* __restrict__ W2, const float* __restrict__ b2,
                         const float* __restrict__ W3, const float* __restrict__ b3,
                         const float* __restrict__ W4, const float* __restrict__ b4,
                         const float* __restrict__ W5, const float* __restrict__ b5) {
    if (blockIdx.x == 0)
        weights_chain(W1, b1, W2, b2, W3, b3, W4, b4, W5, b5);

    int t = (blockIdx.x * blockDim.x + threadIdx.x) * 4;
    if (t >= e2) return;
    int4 a  = *(const int4*)&g_csr[t];       // edges t, t+1
    int4 bb = *(const int4*)&g_csr[t + 2];   // edges t+2, t+3
    int4 dd = *(const int4*)&g_dsta[t];
    float c0 = __int_as_float(a.y),  c1 = __int_as_float(a.w);
    float c2 = __int_as_float(bb.y), c3 = __int_as_float(bb.w);
    float x0 = __ldg(&x[a.x]),  x1 = __ldg(&x[a.w ? a.z : a.z]);  // a.z is src of edge t+1
    x1 = __ldg(&x[a.z]);
    float x2 = __ldg(&x[bb.x]), x3 = __ldg(&x[bb.z]);
    float2 v0 = make_float2(c0 * x0, c0);
    float2 v1 = make_float2(c1 * x1, c1);
    float2 v2 = make_float2(c2 * x2, c2);
    float2 v3 = make_float2(c3 * x3, c3);

    float2* out = g_p[1];
    float2 acc = v0; int cur = dd.x;
    if (dd.y == cur) { acc.x += v1.x; acc.y += v1.y; }
    else { atomicAdd(&out[cur].x, acc.x); atomicAdd(&out[cur].y, acc.y); cur = dd.y; acc = v1; }
    if (dd.z == cur) { acc.x += v2.x; acc.y += v2.y; }
    else { atomicAdd(&out[cur].x, acc.x); atomicAdd(&out[cur].y, acc.y); cur = dd.z; acc = v2; }
    if (dd.w == cur) { acc.x += v3.x; acc.y += v3.y; }
    else { atomicAdd(&out[cur].x, acc.x); atomicAdd(&out[cur].y, acc.y); cur = dd.w; acc = v3; }
    atomicAdd(&out[cur].x, acc.x); atomicAdd(&out[cur].y, acc.y);
}

// ---------------- edge-parallel generic pass: p[kout] += per-edge c * p[kin][src] ----------------
__global__ void k_epass(int e2, int kin, int kout) {
    int t = (blockIdx.x * blockDim.x + threadIdx.x) * 4;
    if (t >= e2) return;
    const float2* __restrict__ vin = g_p[kin];
    int4 a  = *(const int4*)&g_csr[t];
    int4 bb = *(const int4*)&g_csr[t + 2];
    int4 dd = *(const int4*)&g_dsta[t];
    float c0 = __int_as_float(a.y),  c1 = __int_as_float(a.w);
    float c2 = __int_as_float(bb.y), c3 = __int_as_float(bb.w);
    float2 w0 = __ldg(&vin[a.x]);
    float2 w1 = __ldg(&vin[a.z]);
    float2 w2 = __ldg(&vin[bb.x]);
    float2 w3 = __ldg(&vin[bb.z]);
    float2 v0 = make_float2(c0 * w0.x, c0 * w0.y);
    float2 v1 = make_float2(c1 * w1.x, c1 * w1.y);
    float2 v2 = make_float2(c2 * w2.x, c2 * w2.y);
    float2 v3 = make_float2(c3 * w3.x, c3 * w3.y);

    float2* out = g_p[kout];
    float2 acc = v0; int cur = dd.x;
    if (dd.y == cur) { acc.x += v1.x; acc.y += v1.y; }
    else { atomicAdd(&out[cur].x, acc.x); atomicAdd(&out[cur].y, acc.y); cur = dd.y; acc = v1; }
    if (dd.z == cur) { acc.x += v2.x; acc.y += v2.y; }
    else { atomicAdd(&out[cur].x, acc.x); atomicAdd(&out[cur].y, acc.y); cur = dd.z; acc = v2; }
    if (dd.w == cur) { acc.x += v3.x; acc.y += v3.y; }
    else { atomicAdd(&out[cur].x, acc.x); atomicAdd(&out[cur].y, acc.y); cur = dd.w; acc = v3; }
    atomicAdd(&out[cur].x, acc.x); atomicAdd(&out[cur].y, acc.y);
}

// ---------------- pass 5 (x-only, node-parallel; row includes self edge) + final write ----------------
__global__ void k_spmv5_final(int n, float* __restrict__ out) {
    __shared__ float sc[6][100];
    __shared__ float sv5[256], sa1[256], sa2[256], sa3[256], sa4[256];
    for (int t = threadIdx.x; t < 600; t += blockDim.x)
        sc[t / 100][t % 100] = g_c[(t / 100) * 128 + (t % 100)];

    int base = blockIdx.x * 256;
    int i = base + threadIdx.x;

    if (i < n) {
        const float2* __restrict__ vin = g_p[4];
        int e0 = g_off[i], e1 = g_off[i + 1];
        float ax = 0.0f;                         // self edge is in the row
        int e = e0;
        for (; e + 4 <= e1; e += 4) {
            int2 p0 = __ldg(&g_csr[e]);
            int2 p1 = __ldg(&g_csr[e + 1]);
            int2 p2 = __ldg(&g_csr[e + 2]);
            int2 p3 = __ldg(&g_csr[e + 3]);
            float v0 = __ldg(&vin[p0.x].x);
            float v1 = __ldg(&vin[p1.x].x);
            float v2 = __ldg(&vin[p2.x].x);
            float v3 = __ldg(&vin[p3.x].x);
            ax += __int_as_float(p0.y) * v0 + __int_as_float(p1.y) * v1
                + __int_as_float(p2.y) * v2 + __int_as_float(p3.y) * v3;
        }
        for (; e < e1; e++) {
            int2 p = __ldg(&g_csr[e]);
            ax += __int_as_float(p.y) * __ldg(&vin[p.x].x);
        }
        sv5[threadIdx.x] = ax;
        sa1[threadIdx.x] = g_p[1][i].y;
        sa2[threadIdx.x] = g_p[2][i].y;
        sa3[threadIdx.x] = g_p[3][i].y;
        sa4[threadIdx.x] = g_p[4][i].y;
    }
    __syncthreads();

    for (int t = threadIdx.x; t < 256 * 25; t += blockDim.x) {
        int wnode = t / 25;
        int ch = t - wnode * 25;
        int node = base + wnode;
        if (node >= n) break;
        float v5 = sv5[wnode];
        float a1 = sa1[wnode], a2 = sa2[wnode], a3 = sa3[wnode], a4 = sa4[wnode];
        int j0 = ch * 4;
        float4 r;
        float* rr = &r.x;
        #pragma unroll
        for (int q = 0; q < 4; q++) {
            int j = j0 + q;
            rr[q] = fmaxf(v5 * sc[0][j] + a4 * sc[1][j] + a3 * sc[2][j]
                        + a2 * sc[3][j] + a1 * sc[4][j] + sc[5][j], 0.0f);
        }
        ((float4*)(out + (size_t)node * 100))[ch] = r;
    }
}

// ---------------- launch ----------------
extern "C" void kernel_launch(void* const* d_in, const int* in_sizes, int n_in,
                              void* d_out, int out_size) {
    const float* x  = (const float*)d_in[0];
    const int*   ei = (const int*)d_in[1];     // int32!
    const float* ew = (const float*)d_in[2];
    const float* W1 = (const float*)d_in[3];  const float* b1 = (const float*)d_in[4];
    const float* W2 = (const float*)d_in[5];  const float* b2 = (const float*)d_in[6];
    const float* W3 = (const float*)d_in[7];  const float* b3 = (const float*)d_in[8];
    const float* W4 = (const float*)d_in[9];  const float* b4 = (const float*)d_in[10];
    const float* W5 = (const float*)d_in[11]; const float* b5 = (const float*)d_in[12];
    float* out = (float*)d_out;

    int n = in_sizes[0];
    int e = in_sizes[2];
    int e2 = e + n;                    // edges + self loops

    int tb = 256;
    int gbN  = (n + tb - 1) / tb;
    int gbE  = (e + tb - 1) / tb;
    int nb   = (n + 1023) / 1024;
    int tE   = (e2 + 3) / 4;           // one thread per 4 edges
    int gbE2 = (tE + tb - 1) / tb;

    k_init<<<gbN, tb>>>(n);
    k_edge_deg<<<gbE, tb>>>(e, ei, ew);
    k_scan1<<<nb, 1024>>>(n);
    k_scan3f<<<gbN, tb>>>(n, nb, e2);
    k_scatter<<<gbE, tb>>>(e, ei, ew);

    k_epass1<<<gbE2, tb>>>(e2, x, W1, b1, W2, b2, W3, b3, W4, b4, W5, b5);
    k_epass<<<gbE2, tb>>>(e2, 1, 2);
    k_epass<<<gbE2, tb>>>(e2, 2, 3);
    k_epass<<<gbE2, tb>>>(e2, 3, 4);
    k_spmv5_final<<<gbN, tb>>>(n, out);

    (void)n_in; (void)out_size;
}